// round 12
// baseline (speedup 1.0000x reference)
#include <cuda_runtime.h>
#include <cuda_bf16.h>
#include <math.h>
#include <stdint.h>

#define N_NODES 100000
#define NFEAT   256
#define HID     32
#define NCOL    64
#define TILE_M  128
#define NT      782          // ceil(100000/128)

// ---- smem layout (bytes) ----
// A ring: 4 stages x (128 rows x 80B) = 40960   (one k16-chunk per stage)
#define AROW      80
#define ASTAGE    (TILE_M * AROW)          // 10240
#define NSTAGE    4
#define A_OFF     0
#define BROW_B    528
#define B_BYTES   (NCOL * BROW_B)          // 33792
#define B_HI_OFF  (NSTAGE * ASTAGE)        // 40960
#define B_LO_OFF  (B_HI_OFF + B_BYTES)     // 74752
#define BIAS_OFF  (B_LO_OFF + B_BYTES)     // 108544
#define WLIN_OFF  (BIAS_OFF + 256)
#define BLIN_OFF  (WLIN_OFF + 128)
#define SMEM_TOTAL (BLIN_OFF + 16)         // 108944 -> 2 CTAs/SM

// persistent device scratch (natural k-order W, bf16 hi/lo split)
__device__ __nv_bfloat16 g_Whi[NCOL * NFEAT];
__device__ __nv_bfloat16 g_Wlo[NCOL * NFEAT];
__device__ float g_bias[NCOL];
__device__ float g_wlin[HID];
__device__ float g_blin;

__global__ void prep_kernel(const float* __restrict__ Wz, const float* __restrict__ bz,
                            const float* __restrict__ Wh, const float* __restrict__ bh,
                            const float* __restrict__ Wlin, const float* __restrict__ blin)
{
    int idx = blockIdx.x * blockDim.x + threadIdx.x;
    if (idx < NCOL * NFEAT) {
        int n = idx / NFEAT, k = idx % NFEAT;
        const float* W = (n < HID) ? Wz : Wh;               // (2,1,288,32) row-major
        int nn = n & (HID - 1);
        float w = W[k * HID + nn] + W[288 * HID + k * HID + nn];
        __nv_bfloat16 hi = __float2bfloat16(w);
        g_Whi[idx] = hi;
        g_Wlo[idx] = __float2bfloat16(w - __bfloat162float(hi));
    }
    if (blockIdx.x == 0) {
        int t = threadIdx.x;
        if (t < NCOL) g_bias[t] = (t < HID) ? bz[t] : bh[t - HID];
        if (t < HID)  g_wlin[t] = Wlin[t];
        if (t == 0)   g_blin = blin[0];
    }
}

// ---------- helpers ----------
#define MMA(acc, a, b0, b1) \
    asm("mma.sync.aligned.m16n8k16.row.col.f32.bf16.bf16.f32 " \
        "{%0,%1,%2,%3}, {%4,%5,%6,%7}, {%8,%9}, {%0,%1,%2,%3};" \
        : "+f"((acc)[0]), "+f"((acc)[1]), "+f"((acc)[2]), "+f"((acc)[3]) \
        : "r"((a)[0]), "r"((a)[1]), "r"((a)[2]), "r"((a)[3]), "r"(b0), "r"(b1))

#define LDM4(r, addr) \
    asm("ldmatrix.sync.aligned.m8n8.x4.shared.b16 {%0,%1,%2,%3}, [%4];" \
        : "=r"((r)[0]), "=r"((r)[1]), "=r"((r)[2]), "=r"((r)[3]) : "r"(addr))

#define LDS64F(f0, f1, addr) \
    asm("ld.shared.v2.f32 {%0,%1}, [%2];" : "=f"(f0), "=f"(f1) : "r"(addr))

// pack (fx,fy) -> bf16x2 hi (exact round) and bf16x2 of residual
#define CVTHILO2(fx, fy, h, l) do { \
    asm("cvt.rn.bf16x2.f32 %0, %1, %2;" : "=r"(h) : "f"(fy), "f"(fx)); \
    float _rx = (fx) - __uint_as_float((h) << 16); \
    float _ry = (fy) - __uint_as_float((h) & 0xffff0000u); \
    asm("cvt.rn.bf16x2.f32 %0, %1, %2;" : "=r"(l) : "f"(_ry), "f"(_rx)); \
} while (0)

__device__ __forceinline__ void cp_async16(uint32_t sdst, const void* gsrc) {
    asm volatile("cp.async.ca.shared.global [%0], [%1], 16;" :: "r"(sdst), "l"(gsrc));
}
#define CP_COMMIT() asm volatile("cp.async.commit_group;" ::: "memory")
#define CP_WAIT2()  asm volatile("cp.async.wait_group 2;" ::: "memory")

__device__ __forceinline__ float fast_tanh(float v) {
    return 1.0f - 2.0f / (__expf(2.0f * v) + 1.0f);
}

extern __shared__ __align__(128) char smem[];

// stage one k16-chunk (128 rows x 64B) of X into ring buffer `buf`
__device__ __forceinline__ void stage_A(uint32_t sbase, int buf, int ks,
                                        const float* __restrict__ x,
                                        int tile0, int tid)
{
    uint32_t sdst = sbase + A_OFF + buf * ASTAGE;
#pragma unroll
    for (int i = 0; i < 2; i++) {
        int idx = tid + i * 256;       // 0..511
        int r = idx >> 2, c = idx & 3;
        int gr = tile0 + r;
        if (gr >= N_NODES) gr = N_NODES - 1;   // tail clamp; never stored
        cp_async16(sdst + r * AROW + c * 16,
                   x + (size_t)gr * NFEAT + ks * 16 + c * 4);
    }
}

__global__ __launch_bounds__(256, 2)
void gcn_hmma_kernel(const float* __restrict__ x, float* __restrict__ out)
{
    const int tid  = threadIdx.x;
    const uint32_t sbase = (uint32_t)__cvta_generic_to_shared(smem);
    const int tile0 = blockIdx.x * TILE_M;

    // ---- kick off A pipeline (3 stages ahead) ----
    stage_A(sbase, 0, 0, x, tile0, tid); CP_COMMIT();
    stage_A(sbase, 1, 1, x, tile0, tid); CP_COMMIT();
    stage_A(sbase, 2, 2, x, tile0, tid); CP_COMMIT();

    // ---- stage B hi/lo into padded ldmatrix rows (overlaps with cp.async) ----
    {
        const uint2* whi = reinterpret_cast<const uint2*>(g_Whi);
        const uint2* wlo = reinterpret_cast<const uint2*>(g_Wlo);
#pragma unroll
        for (int i = 0; i < 16; i++) {
            int idx = tid + i * 256;          // 0..4095
            int n = idx >> 6, c = idx & 63;
            *reinterpret_cast<uint2*>(smem + B_HI_OFF + n * BROW_B + c * 8) = whi[idx];
            *reinterpret_cast<uint2*>(smem + B_LO_OFF + n * BROW_B + c * 8) = wlo[idx];
        }
    }
    if (tid < NCOL) reinterpret_cast<float*>(smem + BIAS_OFF)[tid] = g_bias[tid];
    if (tid < HID)  reinterpret_cast<float*>(smem + WLIN_OFF)[tid] = g_wlin[tid];
    if (tid == 0)   reinterpret_cast<float*>(smem + BLIN_OFF)[0] = g_blin;
    __syncthreads();

    const int lane = tid & 31;
    const int g = lane >> 2, t = lane & 3;
    const int warp = tid >> 5;

    const int r0 = tile0 + warp * 16 + g, r1 = r0 + 8;

    // ldmatrix per-lane address for B
    const int lm_n = ((lane >> 4) & 1) * 8 + (lane & 7);
    const int lm_k = ((lane >> 3) & 1) * 8;
    const uint32_t lmhi = sbase + B_HI_OFF + lm_n * BROW_B + lm_k * 2;

    // per-lane A smem offset within a stage: row (warp*16+g), col-pair 2t
    const uint32_t a_lane = (uint32_t)((warp * 16 + g) * AROW + t * 8);

    float acc[8][4];
#pragma unroll
    for (int i = 0; i < 8; i++)
#pragma unroll
        for (int j = 0; j < 4; j++) acc[i][j] = 0.0f;

#pragma unroll 1
    for (int ks = 0; ks < 16; ks++) {
        CP_WAIT2();            // stage ks complete (3 in flight, keep <=2 pending)
        __syncthreads();       // data visible to all; prev reads of reused buf done

        if (ks < 13) stage_A(sbase, (ks + 3) & 3, ks + 3, x, tile0, tid);
        CP_COMMIT();           // commit every iter (possibly empty) to keep count

        const uint32_t ab = sbase + A_OFF + (ks & 3) * ASTAGE + a_lane;
        float f00x, f00y, f10x, f10y, f01x, f01y, f11x, f11y;
        LDS64F(f00x, f00y, ab);                 // row g,   cols 2t,2t+1
        LDS64F(f10x, f10y, ab + 8 * AROW);      // row g+8
        LDS64F(f01x, f01y, ab + 32);            // row g,   cols 2t+8,2t+9
        LDS64F(f11x, f11y, ab + 8 * AROW + 32); // row g+8

        uint32_t ah[4], al[4];
        CVTHILO2(f00x, f00y, ah[0], al[0]);
        CVTHILO2(f10x, f10y, ah[1], al[1]);
        CVTHILO2(f01x, f01y, ah[2], al[2]);
        CVTHILO2(f11x, f11y, ah[3], al[3]);

        uint32_t bh[4][4];
#pragma unroll
        for (int nt2 = 0; nt2 < 4; nt2++)
            LDM4(bh[nt2], lmhi + nt2 * (16 * BROW_B) + ks * 32);

#pragma unroll
        for (int nt2 = 0; nt2 < 4; nt2++) {            // hi*hi
            MMA(acc[2 * nt2],     ah, bh[nt2][0], bh[nt2][1]);
            MMA(acc[2 * nt2 + 1], ah, bh[nt2][2], bh[nt2][3]);
        }
#pragma unroll
        for (int nt2 = 0; nt2 < 4; nt2++) {            // lo*hi (reuse bh)
            MMA(acc[2 * nt2],     al, bh[nt2][0], bh[nt2][1]);
            MMA(acc[2 * nt2 + 1], al, bh[nt2][2], bh[nt2][3]);
        }
#pragma unroll
        for (int nt2 = 0; nt2 < 4; nt2++) {            // hi*lo
            uint32_t bl[4];
            LDM4(bl, lmhi + (B_LO_OFF - B_HI_OFF) + nt2 * (16 * BROW_B) + ks * 32);
            MMA(acc[2 * nt2],     ah, bl[0], bl[1]);
            MMA(acc[2 * nt2 + 1], ah, bl[2], bl[3]);
        }
    }

    // ---- epilogue: register/shuffle based ----
    const float* sBias = reinterpret_cast<const float*>(smem + BIAS_OFF);
    const float* sWlin = reinterpret_cast<const float*>(smem + WLIN_OFF);
    const float  blin  = reinterpret_cast<const float*>(smem + BLIN_OFF)[0];

#pragma unroll
    for (int row = 0; row < 2; row++) {
        float s = 0.0f;
#pragma unroll
        for (int nt = 0; nt < 4; nt++) {
#pragma unroll
            for (int j = 0; j < 2; j++) {
                int c = nt * 8 + 2 * t + j;
                float zv = acc[nt][row * 2 + j]     + sBias[c];
                float hv = acc[nt + 4][row * 2 + j] + sBias[HID + c];
                float z  = 1.0f / (1.0f + __expf(-zv));
                float th = fast_tanh(hv);
                float h  = fmaxf((1.0f - z) * th, 0.0f);
                s = fmaf(h, sWlin[c], s);
            }
        }
        s += __shfl_xor_sync(0xffffffffu, s, 1);
        s += __shfl_xor_sync(0xffffffffu, s, 2);
        int node = row ? r1 : r0;
        if (t == 0 && node < N_NODES) out[node] = s + blin;
    }
}

extern "C" void kernel_launch(void* const* d_in, const int* in_sizes, int n_in,
                              void* d_out, int out_size)
{
    const float* x    = (const float*)d_in[0];
    const float* Wz   = (const float*)d_in[3];
    const float* bz   = (const float*)d_in[4];
    const float* Wh   = (const float*)d_in[7];
    const float* bh   = (const float*)d_in[8];
    const float* Wlin = (const float*)d_in[9];
    const float* blin = (const float*)d_in[10];
    float* out = (float*)d_out;

    prep_kernel<<<64, 256>>>(Wz, bz, Wh, bh, Wlin, blin);

    cudaFuncSetAttribute(gcn_hmma_kernel,
                         cudaFuncAttributeMaxDynamicSharedMemorySize, SMEM_TOTAL);
    gcn_hmma_kernel<<<NT, 256, SMEM_TOTAL>>>(x, out);
}

// round 13
// speedup vs baseline: 1.6377x; 1.6377x over previous
#include <cuda_runtime.h>
#include <cuda_fp16.h>
#include <math.h>
#include <stdint.h>

#define N_NODES 100000
#define NFEAT   256
#define HID     32
#define NCOL    64
#define TILE_M  128
#define NT      782          // ceil(100000/128)

// B smem: 64 rows x 264 fp16 (528B padded rows, conflict-free ldmatrix phases)
#define BROW_B   528
#define B_BYTES  (NCOL * BROW_B)     // 33792
#define B_HI_OFF 0
#define BIAS_OFF B_BYTES                   // 64 f32
#define WLIN_OFF (BIAS_OFF + 256)          // 32 f32
#define BLIN_OFF (WLIN_OFF + 128)
#define SMEM_TOTAL (BLIN_OFF + 16)         // ~34.2 KB

// persistent device scratch (prep output; W stored K-PERMUTED within 16-blocks)
__device__ __half g_W16[NCOL * NFEAT];
__device__ float g_bias[NCOL];
__device__ float g_wlin[HID];
__device__ float g_blin;

// logical fragment position p -> physical k within a 16-block, so that lane t's
// float4 at physical cols 4t..4t+3 lands at logical (2t,2t+1,2t+8,2t+9)
__device__ __forceinline__ int kperm(int p) {
    return (p < 8) ? (4 * (p >> 1) + (p & 1))
                   : (4 * ((p - 8) >> 1) + 2 + (p & 1));
}

__global__ void prep_kernel(const float* __restrict__ Wz, const float* __restrict__ bz,
                            const float* __restrict__ Wh, const float* __restrict__ bh,
                            const float* __restrict__ Wlin, const float* __restrict__ blin)
{
    int idx = blockIdx.x * blockDim.x + threadIdx.x;
    if (idx < NCOL * NFEAT) {
        int n = idx / NFEAT, k = idx % NFEAT;               // k = logical position
        int kp = (k & ~15) | kperm(k & 15);                 // physical source col
        const float* W = (n < HID) ? Wz : Wh;               // (2,1,288,32) row-major
        int nn = n & (HID - 1);
        float w = W[kp * HID + nn] + W[288 * HID + kp * HID + nn];
        g_W16[idx] = __float2half_rn(w);
    }
    if (blockIdx.x == 0) {
        int t = threadIdx.x;
        if (t < NCOL) g_bias[t] = (t < HID) ? bz[t] : bh[t - HID];
        if (t < HID)  g_wlin[t] = Wlin[t];
        if (t == 0)   g_blin = blin[0];
    }
}

// ---------- helpers ----------
#define MMA(acc, a, b0, b1) \
    asm("mma.sync.aligned.m16n8k16.row.col.f32.f16.f16.f32 " \
        "{%0,%1,%2,%3}, {%4,%5,%6,%7}, {%8,%9}, {%0,%1,%2,%3};" \
        : "+f"((acc)[0]), "+f"((acc)[1]), "+f"((acc)[2]), "+f"((acc)[3]) \
        : "r"((a)[0]), "r"((a)[1]), "r"((a)[2]), "r"((a)[3]), "r"(b0), "r"(b1))

#define LDM4(r, addr) \
    asm("ldmatrix.sync.aligned.m8n8.x4.shared.b16 {%0,%1,%2,%3}, [%4];" \
        : "=r"((r)[0]), "=r"((r)[1]), "=r"((r)[2]), "=r"((r)[3]) : "r"(addr))

// fp16 two-term split: h = f16x2(fx,fy), l = f16x2 of exact residuals
#define CVTHILO2(fx, fy, h, l) do { \
    asm("cvt.rn.f16x2.f32 %0, %1, %2;" : "=r"(h) : "f"(fy), "f"(fx)); \
    float _hx, _hy; \
    asm("{\n\t.reg .b16 lo, hi;\n\tmov.b32 {lo, hi}, %2;\n\t" \
        "cvt.f32.f16 %0, lo;\n\tcvt.f32.f16 %1, hi;\n\t}" \
        : "=f"(_hx), "=f"(_hy) : "r"(h)); \
    float _rx = (fx) - _hx; \
    float _ry = (fy) - _hy; \
    asm("cvt.rn.f16x2.f32 %0, %1, %2;" : "=r"(l) : "f"(_ry), "f"(_rx)); \
} while (0)

__device__ __forceinline__ float fast_tanh(float v) {
    return 1.0f - 2.0f / (__expf(2.0f * v) + 1.0f);
}

extern __shared__ __align__(128) char smem[];

__global__ __launch_bounds__(256, 3)
void gcn_hmma_kernel(const float* __restrict__ x, float* __restrict__ out)
{
    const int tid  = threadIdx.x;
    const uint32_t sbase = (uint32_t)__cvta_generic_to_shared(smem);

    // ---- stage fp16 W into padded smem rows (8B chunks) ----
    {
        const uint2* w16 = reinterpret_cast<const uint2*>(g_W16);
#pragma unroll
        for (int i = 0; i < 16; i++) {
            int idx = tid + i * 256;          // 0..4095
            int n = idx >> 6, c = idx & 63;   // 64 chunks of 4 fp16 per row
            *reinterpret_cast<uint2*>(smem + B_HI_OFF + n * BROW_B + c * 8) = w16[idx];
        }
    }
    if (tid < NCOL) reinterpret_cast<float*>(smem + BIAS_OFF)[tid] = g_bias[tid];
    if (tid < HID)  reinterpret_cast<float*>(smem + WLIN_OFF)[tid] = g_wlin[tid];
    if (tid == 0)   reinterpret_cast<float*>(smem + BLIN_OFF)[0] = g_blin;
    __syncthreads();

    const int warp = tid >> 5, lane = tid & 31;
    const int g = lane >> 2, t = lane & 3;

    const int nodeBase = blockIdx.x * TILE_M + warp * 16;
    const int r0 = nodeBase + g, r1 = r0 + 8;
    const int cr0 = (r0 < N_NODES) ? r0 : (N_NODES - 1);
    const int cr1 = (r1 < N_NODES) ? r1 : (N_NODES - 1);
    const float4* p0 = reinterpret_cast<const float4*>(x) + (size_t)cr0 * 64 + t;
    const float4* p1 = reinterpret_cast<const float4*>(x) + (size_t)cr1 * 64 + t;

    // ldmatrix per-lane address (logical layout; matches permuted-stored W)
    const int lm_n = ((lane >> 4) & 1) * 8 + (lane & 7);
    const int lm_k = ((lane >> 3) & 1) * 8;
    const uint32_t lmhi = sbase + B_HI_OFF + lm_n * BROW_B + lm_k * 2;

    float acc[8][4];
#pragma unroll
    for (int i = 0; i < 8; i++)
#pragma unroll
        for (int j = 0; j < 4; j++) acc[i][j] = 0.0f;

#pragma unroll 2
    for (int ks = 0; ks < 16; ks++) {
        float4 v0 = __ldg(p0 + ks * 4);   // row r0: logical k (2t,2t+1),(2t+8,2t+9)
        float4 v1 = __ldg(p1 + ks * 4);   // row r1

        uint32_t ah[4], al[4];
        CVTHILO2(v0.x, v0.y, ah[0], al[0]);
        CVTHILO2(v1.x, v1.y, ah[1], al[1]);
        CVTHILO2(v0.z, v0.w, ah[2], al[2]);
        CVTHILO2(v1.z, v1.w, ah[3], al[3]);

        // keep all B fragments live; two de-clustered passes so consecutive
        // MMAs on the same accumulator are ~8 issues apart
        uint32_t bh[4][4];
#pragma unroll
        for (int nt2 = 0; nt2 < 4; nt2++)
            LDM4(bh[nt2], lmhi + nt2 * (16 * BROW_B) + ks * 32);

#pragma unroll
        for (int nt2 = 0; nt2 < 4; nt2++) {            // pass 1: x_hi * W
            MMA(acc[2 * nt2],     ah, bh[nt2][0], bh[nt2][1]);
            MMA(acc[2 * nt2 + 1], ah, bh[nt2][2], bh[nt2][3]);
        }
#pragma unroll
        for (int nt2 = 0; nt2 < 4; nt2++) {            // pass 2: x_lo * W (reuse bh)
            MMA(acc[2 * nt2],     al, bh[nt2][0], bh[nt2][1]);
            MMA(acc[2 * nt2 + 1], al, bh[nt2][2], bh[nt2][3]);
        }
    }

    // ---- epilogue: fully register/shuffle based ----
    const float* sBias = reinterpret_cast<const float*>(smem + BIAS_OFF);
    const float* sWlin = reinterpret_cast<const float*>(smem + WLIN_OFF);
    const float  blin  = reinterpret_cast<const float*>(smem + BLIN_OFF)[0];

#pragma unroll
    for (int row = 0; row < 2; row++) {
        float s = 0.0f;
#pragma unroll
        for (int nt = 0; nt < 4; nt++) {
#pragma unroll
            for (int j = 0; j < 2; j++) {
                int c = nt * 8 + 2 * t + j;
                float zv = acc[nt][row * 2 + j]     + sBias[c];
                float hv = acc[nt + 4][row * 2 + j] + sBias[HID + c];
                float z  = 1.0f / (1.0f + __expf(-zv));
                float th = fast_tanh(hv);
                float h  = fmaxf((1.0f - z) * th, 0.0f);
                s = fmaf(h, sWlin[c], s);
            }
        }
        s += __shfl_xor_sync(0xffffffffu, s, 1);
        s += __shfl_xor_sync(0xffffffffu, s, 2);
        int node = row ? r1 : r0;
        if (t == 0 && node < N_NODES) out[node] = s + blin;
    }
}

extern "C" void kernel_launch(void* const* d_in, const int* in_sizes, int n_in,
                              void* d_out, int out_size)
{
    const float* x    = (const float*)d_in[0];
    const float* Wz   = (const float*)d_in[3];
    const float* bz   = (const float*)d_in[4];
    const float* Wh   = (const float*)d_in[7];
    const float* bh   = (const float*)d_in[8];
    const float* Wlin = (const float*)d_in[9];
    const float* blin = (const float*)d_in[10];
    float* out = (float*)d_out;

    prep_kernel<<<64, 256>>>(Wz, bz, Wh, bh, Wlin, blin);

    cudaFuncSetAttribute(gcn_hmma_kernel,
                         cudaFuncAttributeMaxDynamicSharedMemorySize, SMEM_TOTAL);
    gcn_hmma_kernel<<<NT, 256, SMEM_TOTAL>>>(x, out);
}

// round 14
// speedup vs baseline: 1.8171x; 1.1095x over previous
#include <cuda_runtime.h>
#include <cuda_fp16.h>
#include <math.h>
#include <stdint.h>

#define N_NODES 100000
#define NFEAT   256
#define HID     32
#define NCOL    64
#define TILE_M  128
#define NT      782          // ceil(100000/128)

// B smem: 64 rows x 264 fp16 (528B padded rows, conflict-free ldmatrix phases)
#define BROW_B   528
#define B_BYTES  (NCOL * BROW_B)     // 33792
#define B_HI_OFF 0
#define BIAS_OFF B_BYTES                   // 64 f32
#define WLIN_OFF (BIAS_OFF + 256)          // 32 f32
#define BLIN_OFF (WLIN_OFF + 128)
#define SMEM_TOTAL (BLIN_OFF + 16)         // ~34.2 KB -> 4 CTAs/SM

// persistent device scratch (prep output; W stored K-PERMUTED within 16-blocks)
__device__ __half g_W16[NCOL * NFEAT];
__device__ float g_bias[NCOL];
__device__ float g_wlin[HID];
__device__ float g_blin;

// logical fragment position p -> physical k within a 16-block, so that lane t's
// float4 at physical cols 4t..4t+3 lands at logical (2t,2t+1,2t+8,2t+9)
__device__ __forceinline__ int kperm(int p) {
    return (p < 8) ? (4 * (p >> 1) + (p & 1))
                   : (4 * ((p - 8) >> 1) + 2 + (p & 1));
}

__global__ void prep_kernel(const float* __restrict__ Wz, const float* __restrict__ bz,
                            const float* __restrict__ Wh, const float* __restrict__ bh,
                            const float* __restrict__ Wlin, const float* __restrict__ blin)
{
    int idx = blockIdx.x * blockDim.x + threadIdx.x;
    if (idx < NCOL * NFEAT) {
        int n = idx / NFEAT, k = idx % NFEAT;               // k = logical position
        int kp = (k & ~15) | kperm(k & 15);                 // physical source col
        const float* W = (n < HID) ? Wz : Wh;               // (2,1,288,32) row-major
        int nn = n & (HID - 1);
        float w = W[kp * HID + nn] + W[288 * HID + kp * HID + nn];
        g_W16[idx] = __float2half_rn(w);
    }
    if (blockIdx.x == 0) {
        int t = threadIdx.x;
        if (t < NCOL) g_bias[t] = (t < HID) ? bz[t] : bh[t - HID];
        if (t < HID)  g_wlin[t] = Wlin[t];
        if (t == 0)   g_blin = blin[0];
    }
}

// ---------- helpers ----------
#define MMA(acc, a, b0, b1) \
    asm("mma.sync.aligned.m16n8k16.row.col.f32.f16.f16.f32 " \
        "{%0,%1,%2,%3}, {%4,%5,%6,%7}, {%8,%9}, {%0,%1,%2,%3};" \
        : "+f"((acc)[0]), "+f"((acc)[1]), "+f"((acc)[2]), "+f"((acc)[3]) \
        : "r"((a)[0]), "r"((a)[1]), "r"((a)[2]), "r"((a)[3]), "r"(b0), "r"(b1))

#define LDM4(r, addr) \
    asm("ldmatrix.sync.aligned.m8n8.x4.shared.b16 {%0,%1,%2,%3}, [%4];" \
        : "=r"((r)[0]), "=r"((r)[1]), "=r"((r)[2]), "=r"((r)[3]) : "r"(addr))

// pack (fx,fy) -> fp16x2
#define CVT2(h, fx, fy) \
    asm("cvt.rn.f16x2.f32 %0, %1, %2;" : "=r"(h) : "f"(fy), "f"(fx))

__device__ __forceinline__ float fast_tanh(float v) {
    return 1.0f - 2.0f / (__expf(2.0f * v) + 1.0f);
}

extern __shared__ __align__(128) char smem[];

__global__ __launch_bounds__(256, 4)
void gcn_hmma_kernel(const float* __restrict__ x, float* __restrict__ out)
{
    const int tid  = threadIdx.x;
    const uint32_t sbase = (uint32_t)__cvta_generic_to_shared(smem);

    // ---- stage fp16 W into padded smem rows (8B chunks) ----
    {
        const uint2* w16 = reinterpret_cast<const uint2*>(g_W16);
#pragma unroll
        for (int i = 0; i < 16; i++) {
            int idx = tid + i * 256;          // 0..4095
            int n = idx >> 6, c = idx & 63;   // 64 chunks of 4 fp16 per row
            *reinterpret_cast<uint2*>(smem + B_HI_OFF + n * BROW_B + c * 8) = w16[idx];
        }
    }
    if (tid < NCOL) reinterpret_cast<float*>(smem + BIAS_OFF)[tid] = g_bias[tid];
    if (tid < HID)  reinterpret_cast<float*>(smem + WLIN_OFF)[tid] = g_wlin[tid];
    if (tid == 0)   reinterpret_cast<float*>(smem + BLIN_OFF)[0] = g_blin;
    __syncthreads();

    const int warp = tid >> 5, lane = tid & 31;
    const int g = lane >> 2, t = lane & 3;

    const int nodeBase = blockIdx.x * TILE_M + warp * 16;
    const int r0 = nodeBase + g, r1 = r0 + 8;
    const int cr0 = (r0 < N_NODES) ? r0 : (N_NODES - 1);
    const int cr1 = (r1 < N_NODES) ? r1 : (N_NODES - 1);
    const float4* p0 = reinterpret_cast<const float4*>(x) + (size_t)cr0 * 64 + t;
    const float4* p1 = reinterpret_cast<const float4*>(x) + (size_t)cr1 * 64 + t;

    // ldmatrix per-lane address (logical layout; matches permuted-stored W)
    const int lm_n = ((lane >> 4) & 1) * 8 + (lane & 7);
    const int lm_k = ((lane >> 3) & 1) * 8;
    const uint32_t lmhi = sbase + B_HI_OFF + lm_n * BROW_B + lm_k * 2;

    float acc[8][4];
#pragma unroll
    for (int i = 0; i < 8; i++)
#pragma unroll
        for (int j = 0; j < 4; j++) acc[i][j] = 0.0f;

#pragma unroll 2
    for (int ks = 0; ks < 16; ks++) {
        float4 v0 = __ldg(p0 + ks * 4);   // row r0: logical k (2t,2t+1),(2t+8,2t+9)
        float4 v1 = __ldg(p1 + ks * 4);   // row r1

        uint32_t a[4];
        CVT2(a[0], v0.x, v0.y);
        CVT2(a[1], v1.x, v1.y);
        CVT2(a[2], v0.z, v0.w);
        CVT2(a[3], v1.z, v1.w);

#pragma unroll
        for (int nt2 = 0; nt2 < 4; nt2++) {
            uint32_t bh[4];
            LDM4(bh, lmhi + nt2 * (16 * BROW_B) + ks * 32);
            MMA(acc[2 * nt2],     a, bh[0], bh[1]);
            MMA(acc[2 * nt2 + 1], a, bh[2], bh[3]);
        }
    }

    // ---- epilogue: fully register/shuffle based ----
    const float* sBias = reinterpret_cast<const float*>(smem + BIAS_OFF);
    const float* sWlin = reinterpret_cast<const float*>(smem + WLIN_OFF);
    const float  blin  = reinterpret_cast<const float*>(smem + BLIN_OFF)[0];

#pragma unroll
    for (int row = 0; row < 2; row++) {
        float s = 0.0f;
#pragma unroll
        for (int nt = 0; nt < 4; nt++) {
#pragma unroll
            for (int j = 0; j < 2; j++) {
                int c = nt * 8 + 2 * t + j;
                float zv = acc[nt][row * 2 + j]     + sBias[c];
                float hv = acc[nt + 4][row * 2 + j] + sBias[HID + c];
                float z  = 1.0f / (1.0f + __expf(-zv));
                float th = fast_tanh(hv);
                float h  = fmaxf((1.0f - z) * th, 0.0f);
                s = fmaf(h, sWlin[c], s);
            }
        }
        s += __shfl_xor_sync(0xffffffffu, s, 1);
        s += __shfl_xor_sync(0xffffffffu, s, 2);
        int node = row ? r1 : r0;
        if (t == 0 && node < N_NODES) out[node] = s + blin;
    }
}

extern "C" void kernel_launch(void* const* d_in, const int* in_sizes, int n_in,
                              void* d_out, int out_size)
{
    const float* x    = (const float*)d_in[0];
    const float* Wz   = (const float*)d_in[3];
    const float* bz   = (const float*)d_in[4];
    const float* Wh   = (const float*)d_in[7];
    const float* bh   = (const float*)d_in[8];
    const float* Wlin = (const float*)d_in[9];
    const float* blin = (const float*)d_in[10];
    float* out = (float*)d_out;

    prep_kernel<<<64, 256>>>(Wz, bz, Wh, bh, Wlin, blin);

    cudaFuncSetAttribute(gcn_hmma_kernel,
                         cudaFuncAttributeMaxDynamicSharedMemorySize, SMEM_TOTAL);
    gcn_hmma_kernel<<<NT, 256, SMEM_TOTAL>>>(x, out);
}

// round 15
// speedup vs baseline: 1.9652x; 1.0815x over previous
#include <cuda_runtime.h>
#include <cuda_fp16.h>
#include <math.h>
#include <stdint.h>

#define N_NODES 100000
#define NFEAT   256
#define HID     32
#define NCOL    64
#define TILE_M  128
#define NT      782          // ceil(100000/128)

// B smem: 64 rows x 264 fp16 (528B padded rows, conflict-free ldmatrix phases)
#define BROW_B   528
#define B_BYTES  (NCOL * BROW_B)     // 33792
#define B_HI_OFF 0
#define BIAS_OFF B_BYTES                   // 64 f32
#define WLIN_OFF (BIAS_OFF + 256)          // 32 f32
#define BLIN_OFF (WLIN_OFF + 128)
#define SMEM_TOTAL (BLIN_OFF + 16)         // ~34.2 KB

// persistent device scratch (prep output; W stored K-PERMUTED within 16-blocks)
__device__ __half g_W16[NCOL * NFEAT];
__device__ float g_bias[NCOL];
__device__ float g_wlin[HID];
__device__ float g_blin;

// logical fragment position p -> physical k within a 16-block, so that lane t's
// float4 at physical cols 4t..4t+3 lands at logical (2t,2t+1,2t+8,2t+9)
__device__ __forceinline__ int kperm(int p) {
    return (p < 8) ? (4 * (p >> 1) + (p & 1))
                   : (4 * ((p - 8) >> 1) + 2 + (p & 1));
}

__global__ void prep_kernel(const float* __restrict__ Wz, const float* __restrict__ bz,
                            const float* __restrict__ Wh, const float* __restrict__ bh,
                            const float* __restrict__ Wlin, const float* __restrict__ blin)
{
    int idx = blockIdx.x * blockDim.x + threadIdx.x;
    if (idx < NCOL * NFEAT) {
        int n = idx / NFEAT, k = idx % NFEAT;               // k = logical position
        int kp = (k & ~15) | kperm(k & 15);                 // physical source col
        const float* W = (n < HID) ? Wz : Wh;               // (2,1,288,32) row-major
        int nn = n & (HID - 1);
        float w = W[kp * HID + nn] + W[288 * HID + kp * HID + nn];
        g_W16[idx] = __float2half_rn(w);
    }
    if (blockIdx.x == 0) {
        int t = threadIdx.x;
        if (t < NCOL) g_bias[t] = (t < HID) ? bz[t] : bh[t - HID];
        if (t < HID)  g_wlin[t] = Wlin[t];
        if (t == 0)   g_blin = blin[0];
    }
}

// ---------- helpers ----------
#define MMA(acc, a, b0, b1) \
    asm("mma.sync.aligned.m16n8k16.row.col.f32.f16.f16.f32 " \
        "{%0,%1,%2,%3}, {%4,%5,%6,%7}, {%8,%9}, {%0,%1,%2,%3};" \
        : "+f"((acc)[0]), "+f"((acc)[1]), "+f"((acc)[2]), "+f"((acc)[3]) \
        : "r"((a)[0]), "r"((a)[1]), "r"((a)[2]), "r"((a)[3]), "r"(b0), "r"(b1))

#define LDM4(r, addr) \
    asm("ldmatrix.sync.aligned.m8n8.x4.shared.b16 {%0,%1,%2,%3}, [%4];" \
        : "=r"((r)[0]), "=r"((r)[1]), "=r"((r)[2]), "=r"((r)[3]) : "r"(addr))

// pack (fx,fy) -> fp16x2
#define CVT2(h, fx, fy) \
    asm("cvt.rn.f16x2.f32 %0, %1, %2;" : "=r"(h) : "f"(fy), "f"(fx))

// streaming 128b load (evict-first: x is read exactly once)
#define LDG_CS(v, p) \
    asm("ld.global.cs.v4.f32 {%0,%1,%2,%3}, [%4];" \
        : "=f"((v).x), "=f"((v).y), "=f"((v).z), "=f"((v).w) : "l"(p))

__device__ __forceinline__ float fast_tanh(float v) {
    return 1.0f - 2.0f / (__expf(2.0f * v) + 1.0f);
}

extern __shared__ __align__(128) char smem[];

__global__ __launch_bounds__(256, 3)
void gcn_hmma_kernel(const float* __restrict__ x, float* __restrict__ out)
{
    const int tid  = threadIdx.x;
    const uint32_t sbase = (uint32_t)__cvta_generic_to_shared(smem);

    const int warp = tid >> 5, lane = tid & 31;
    const int g = lane >> 2, t = lane & 3;

    const int nodeBase = blockIdx.x * TILE_M + warp * 16;
    const int r0 = nodeBase + g, r1 = r0 + 8;
    const int cr0 = (r0 < N_NODES) ? r0 : (N_NODES - 1);
    const int cr1 = (r1 < N_NODES) ? r1 : (N_NODES - 1);
    const float4* p0 = reinterpret_cast<const float4*>(x) + (size_t)cr0 * 64 + t;
    const float4* p1 = reinterpret_cast<const float4*>(x) + (size_t)cr1 * 64 + t;

    // issue first k-step's loads immediately; they complete during B staging
    float4 c0, c1;
    LDG_CS(c0, p0);
    LDG_CS(c1, p1);

    // ---- stage fp16 W into padded smem rows (8B chunks) ----
    {
        const uint2* w16 = reinterpret_cast<const uint2*>(g_W16);
#pragma unroll
        for (int i = 0; i < 16; i++) {
            int idx = tid + i * 256;          // 0..4095
            int n = idx >> 6, c = idx & 63;   // 64 chunks of 4 fp16 per row
            *reinterpret_cast<uint2*>(smem + B_HI_OFF + n * BROW_B + c * 8) = w16[idx];
        }
    }
    if (tid < NCOL) reinterpret_cast<float*>(smem + BIAS_OFF)[tid] = g_bias[tid];
    if (tid < HID)  reinterpret_cast<float*>(smem + WLIN_OFF)[tid] = g_wlin[tid];
    if (tid == 0)   reinterpret_cast<float*>(smem + BLIN_OFF)[0] = g_blin;
    __syncthreads();

    // ldmatrix per-lane address (logical layout; matches permuted-stored W)
    const int lm_n = ((lane >> 4) & 1) * 8 + (lane & 7);
    const int lm_k = ((lane >> 3) & 1) * 8;
    const uint32_t lmhi = sbase + B_HI_OFF + lm_n * BROW_B + lm_k * 2;

    float acc[8][4];
#pragma unroll
    for (int i = 0; i < 8; i++)
#pragma unroll
        for (int j = 0; j < 4; j++) acc[i][j] = 0.0f;

#pragma unroll 2
    for (int ks = 0; ks < 16; ks++) {
        // 1-deep pipeline: issue next step's loads before consuming this step's
        float4 n0, n1;
        if (ks < 15) {
            LDG_CS(n0, p0 + (ks + 1) * 4);
            LDG_CS(n1, p1 + (ks + 1) * 4);
        }

        uint32_t a[4];
        CVT2(a[0], c0.x, c0.y);
        CVT2(a[1], c1.x, c1.y);
        CVT2(a[2], c0.z, c0.w);
        CVT2(a[3], c1.z, c1.w);

#pragma unroll
        for (int nt2 = 0; nt2 < 4; nt2++) {
            uint32_t bh[4];
            LDM4(bh, lmhi + nt2 * (16 * BROW_B) + ks * 32);
            MMA(acc[2 * nt2],     a, bh[0], bh[1]);
            MMA(acc[2 * nt2 + 1], a, bh[2], bh[3]);
        }

        c0 = n0;
        c1 = n1;
    }

    // ---- epilogue: fully register/shuffle based ----
    const float* sBias = reinterpret_cast<const float*>(smem + BIAS_OFF);
    const float* sWlin = reinterpret_cast<const float*>(smem + WLIN_OFF);
    const float  blin  = reinterpret_cast<const float*>(smem + BLIN_OFF)[0];

#pragma unroll
    for (int row = 0; row < 2; row++) {
        float s = 0.0f;
#pragma unroll
        for (int nt = 0; nt < 4; nt++) {
#pragma unroll
            for (int j = 0; j < 2; j++) {
                int c = nt * 8 + 2 * t + j;
                float zv = acc[nt][row * 2 + j]     + sBias[c];
                float hv = acc[nt + 4][row * 2 + j] + sBias[HID + c];
                float z  = 1.0f / (1.0f + __expf(-zv));
                float th = fast_tanh(hv);
                float h  = fmaxf((1.0f - z) * th, 0.0f);
                s = fmaf(h, sWlin[c], s);
            }
        }
        s += __shfl_xor_sync(0xffffffffu, s, 1);
        s += __shfl_xor_sync(0xffffffffu, s, 2);
        int node = row ? r1 : r0;
        if (t == 0 && node < N_NODES) out[node] = s + blin;
    }
}

extern "C" void kernel_launch(void* const* d_in, const int* in_sizes, int n_in,
                              void* d_out, int out_size)
{
    const float* x    = (const float*)d_in[0];
    const float* Wz   = (const float*)d_in[3];
    const float* bz   = (const float*)d_in[4];
    const float* Wh   = (const float*)d_in[7];
    const float* bh   = (const float*)d_in[8];
    const float* Wlin = (const float*)d_in[9];
    const float* blin = (const float*)d_in[10];
    float* out = (float*)d_out;

    prep_kernel<<<64, 256>>>(Wz, bz, Wh, bh, Wlin, blin);

    cudaFuncSetAttribute(gcn_hmma_kernel,
                         cudaFuncAttributeMaxDynamicSharedMemorySize, SMEM_TOTAL);
    gcn_hmma_kernel<<<NT, 256, SMEM_TOTAL>>>(x, out);
}